// round 17
// baseline (speedup 1.0000x reference)
#include <cuda_runtime.h>
#include <cuda_bf16.h>

// ---------------------------------------------------------------------------
// SSIM (11x11 Gaussian, sigma=1.5, SAME zero padding) over 32x3x512x512 fp32.
// R16: streaming-slab design. TILE 32x128 per CTA, processed in 5 slabs of
// 28 rows: cp.async-staged Q slab (zero-fill OOB) -> horizontal conv into a
// 40-row H ring buffer -> vertical conv + epilogue emitted in row batches.
// Kills the 4x-redundant stage-2 LDG (70% of L1 wavefronts in R15) while
// keeping 32 warps/SM. Math per output identical to R15.
// Deterministic two-stage reduction.
// ---------------------------------------------------------------------------

#define IMG_H 512
#define IMG_W 512
#define N_PLANES 96            // 32 * 3
#define TILE_X 32
#define TILE_Y 128
#define HALO 5
#define LOADY 138              // TILE_Y + 2*HALO
#define SLAB 28
#define NSLAB 5
#define RING 40                // H ring rows (>= 38 needed)
#define QROWS 28
#define QCOLS 48               // staged cols: covers groups mi=0..8
#define W36 36
#define NBLK_X 16
#define NBLK_Y 4
#define NPART (NBLK_X * NBLK_Y * N_PLANES)  // 6144
#define NPART2 24
#define NPIX (32.0 * 3.0 * 512.0 * 512.0)

#define C1F 0.0001f
#define C2F 0.0009f

__device__ constexpr double G0 = 0.003865920;
__device__ constexpr double G1 = 0.028565467;
__device__ constexpr double G2 = 0.135335283;
__device__ constexpr double G3 = 0.411111966;
__device__ constexpr double G4 = 0.800737403;
__device__ constexpr double G5 = 1.0;
__device__ constexpr double GS = G5 + 2.0 * (G0 + G1 + G2 + G3 + G4);
__device__ constexpr float W11[11] = {
    (float)(G0 / GS), (float)(G1 / GS), (float)(G2 / GS), (float)(G3 / GS),
    (float)(G4 / GS), (float)(G5 / GS), (float)(G4 / GS), (float)(G3 / GS),
    (float)(G2 / GS), (float)(G1 / GS), (float)(G0 / GS)};

__device__ float g_partial[NPART];
__device__ float g_partial2[NPART2];

// smem float offsets
#define OFF_H01 0
#define OFF_H23 (RING * W36 * 2)              // 2880
#define OFF_H4  (OFF_H23 + RING * W36 * 2)    // 5760
#define OFF_Q   (OFF_H4 + RING * W36)         // 7200
#define SMEM_FLOATS (OFF_Q + 2 * QROWS * QCOLS)  // 9888 floats = 39552 B
#define SMEM_BYTES (SMEM_FLOATS * 4)

__global__ __launch_bounds__(256, 4) void ssim_tile_kernel(
    const float* __restrict__ img1, const float* __restrict__ img2)
{
    extern __shared__ float smem[];
    float* H01 = smem + OFF_H01;   // [RING][W36][2] (mu1,mu2)
    float* H23 = smem + OFF_H23;   // [RING][W36][2] (ex2,ey2)
    float* H4  = smem + OFF_H4;    // [RING][W36]    (exy)
    float* Q   = smem + OFF_Q;     // [2][QROWS][QCOLS]
    float* red = Q;                // reduction aliases Q (dead by then)

    const int tid = threadIdx.x;
    const int plane = blockIdx.z;
    const int bx = blockIdx.x;
    const int by = blockIdx.y;
    const int ty0 = by * TILE_Y - HALO;
    const int gx0 = bx * TILE_X - 8;   // staged local col c <-> global gx0+c
    const float* p1 = img1 + (size_t)plane * IMG_H * IMG_W;
    const float* p2 = img2 + (size_t)plane * IMG_H * IMG_W;

    const unsigned qbase = (unsigned)__cvta_generic_to_shared(Q);

    // ---- slab loader: cp.async 4B with zero-fill for OOB ----
    auto load_slab = [&](int s) {
        int rows = LOADY - s * SLAB; if (rows > SLAB) rows = SLAB;
        int n = rows * 2 * QCOLS;
        for (int i = tid; i < n; i += 256) {
            int r = i / (2 * QCOLS);
            int rem = i - r * (2 * QCOLS);
            int img = rem >= QCOLS;
            int c = rem - img * QCOLS;
            int gy = ty0 + s * SLAB + r;
            int gx = gx0 + c;
            bool ok = (gy >= 0) & (gy < IMG_H) & (gx >= 0) & (gx < IMG_W);
            const float* base = img ? p2 : p1;
            const float* g = ok ? (base + gy * IMG_W + gx) : base;
            unsigned d = qbase + (unsigned)(((img * QROWS + r) * QCOLS + c) * 4);
            int sz = ok ? 4 : 0;
            asm volatile("cp.async.ca.shared.global [%0], [%1], 4, %2;"
                         :: "r"(d), "l"(g), "r"(sz));
        }
        asm volatile("cp.async.commit_group;" ::: "memory");
    };

    load_slab(0);

    float local = 0.f;
#pragma unroll 1
    for (int s = 0; s < NSLAB; s++) {
        asm volatile("cp.async.wait_group 0;" ::: "memory");
        __syncthreads();

        // ---- horizontal 11-tap pass for this slab (one task per thread) ----
        int rows = LOADY - s * SLAB; if (rows > SLAB) rows = SLAB;
        if (tid < rows * 9) {
            int r = tid / 9;
            int mi = tid - r * 9;
            int abs_r = s * SLAB + r;
            int hr = abs_r % RING;
            float av[16], bv[16];
            {
                const float4* sa = (const float4*)&Q[(0 * QROWS + r) * QCOLS + 4 * mi];
                const float4* sb = (const float4*)&Q[(1 * QROWS + r) * QCOLS + 4 * mi];
#pragma unroll
                for (int t = 0; t < 4; t++) {
                    float4 fa = sa[t], fb = sb[t];
                    av[4 * t + 0] = fa.x; av[4 * t + 1] = fa.y;
                    av[4 * t + 2] = fa.z; av[4 * t + 3] = fa.w;
                    bv[4 * t + 0] = fb.x; bv[4 * t + 1] = fb.y;
                    bv[4 * t + 2] = fb.z; bv[4 * t + 3] = fb.w;
                }
            }
            float acc[5][4];
#pragma unroll
            for (int qi = 0; qi < 5; qi++)
#pragma unroll
                for (int j = 0; j < 4; j++) acc[qi][j] = 0.f;
#pragma unroll
            for (int k = 0; k < 14; k++) {
                float a = av[k], b = bv[k];
                float aa = a * a, bb = b * b, ab = a * b;
#pragma unroll
                for (int j = 0; j < 4; j++) {
                    const int wi = k - j;
                    if (wi >= 0 && wi < 11) {
                        acc[0][j] = fmaf(W11[wi], a,  acc[0][j]);
                        acc[1][j] = fmaf(W11[wi], b,  acc[1][j]);
                        acc[2][j] = fmaf(W11[wi], aa, acc[2][j]);
                        acc[3][j] = fmaf(W11[wi], bb, acc[3][j]);
                        acc[4][j] = fmaf(W11[wi], ab, acc[4][j]);
                    }
                }
            }
            int sc = 4 * mi;
            float4* d01 = (float4*)&H01[(hr * W36 + sc) * 2];
            float4* d23 = (float4*)&H23[(hr * W36 + sc) * 2];
            d01[0] = make_float4(acc[0][0], acc[1][0], acc[0][1], acc[1][1]);
            d01[1] = make_float4(acc[0][2], acc[1][2], acc[0][3], acc[1][3]);
            d23[0] = make_float4(acc[2][0], acc[3][0], acc[2][1], acc[3][1]);
            d23[1] = make_float4(acc[2][2], acc[3][2], acc[2][3], acc[3][3]);
            *(float4*)&H4[hr * W36 + sc] =
                make_float4(acc[4][0], acc[4][1], acc[4][2], acc[4][3]);
        }
        __syncthreads();

        // prefetch next slab while vertical pass runs (Q is free: hconv done)
        if (s + 1 < NSLAB) load_slab(s + 1);

        // ---- vertical 11-tap pass + epilogue for this slab's batch ----
        int e0 = s ? (SLAB * s - 10) : 0;
        int e1 = (s < NSLAB - 1) ? (SLAB * s + 18) : TILE_Y;
        int grps = (e1 - e0 + 3) >> 2;
        int rg = tid >> 5;
        if (rg < grps) {
            int c = tid & 31;
            int o0 = e0 + rg * 4;      // output rows o0..o0+3
            int r00 = o0 % RING;
            float acc[5][4];
#pragma unroll
            for (int qi = 0; qi < 5; qi++)
#pragma unroll
                for (int j = 0; j < 4; j++) acc[qi][j] = 0.f;
#pragma unroll
            for (int k = 0; k < 14; k++) {
                int rk = r00 + k; if (rk >= RING) rk -= RING;
                float2 vab = *(const float2*)&H01[(rk * W36 + c + 3) * 2];
                float2 vsq = *(const float2*)&H23[(rk * W36 + c + 3) * 2];
                float vxy = H4[rk * W36 + c + 3];
#pragma unroll
                for (int j = 0; j < 4; j++) {
                    const int wi = k - j;
                    if (wi >= 0 && wi < 11) {
                        acc[0][j] = fmaf(W11[wi], vab.x, acc[0][j]);
                        acc[1][j] = fmaf(W11[wi], vab.y, acc[1][j]);
                        acc[2][j] = fmaf(W11[wi], vsq.x, acc[2][j]);
                        acc[3][j] = fmaf(W11[wi], vsq.y, acc[3][j]);
                        acc[4][j] = fmaf(W11[wi], vxy,   acc[4][j]);
                    }
                }
            }
#pragma unroll
            for (int j = 0; j < 4; j++) {
                if (o0 + j < e1) {
                    float mu1 = acc[0][j], mu2 = acc[1][j];
                    float ex2 = acc[2][j], ey2 = acc[3][j], exy = acc[4][j];
                    float mu1s = mu1 * mu1, mu2s = mu2 * mu2, mu12 = mu1 * mu2;
                    float s1q = fmaxf(ex2 - mu1s, 0.f);
                    float s2q = fmaxf(ey2 - mu2s, 0.f);
                    float s12 = exy - mu12;
                    float sp = sqrtf(s1q * s2q);
                    float num = (2.f * mu12 + C1F) * (2.f * sp + C2F) * (s12 + 0.5f * C2F);
                    float den = (mu1s + mu2s + C1F) * (s1q + s2q + C2F) * (sp + 0.5f * C2F);
                    local += __fdividef(num, den);
                }
            }
        }
        // next iteration's wait+syncthreads orders vconv reads vs ring reuse
    }

    // ---- Block reduction (red aliases Q; all Q use finished) ----
    __syncthreads();
    red[tid] = local;
    __syncthreads();
#pragma unroll
    for (int st = 128; st > 0; st >>= 1) {
        if (tid < st) red[tid] += red[tid + st];
        __syncthreads();
    }
    if (tid == 0) {
        int bid = (plane * NBLK_Y + by) * NBLK_X + bx;
        g_partial[bid] = red[0];
    }
}

// Stage A: 24 blocks, each sums 256 contiguous partials (deterministic tree).
__global__ __launch_bounds__(256) void ssim_reduceA_kernel()
{
    __shared__ float red[256];
    const int tid = threadIdx.x;
    red[tid] = g_partial[blockIdx.x * 256 + tid];
    __syncthreads();
#pragma unroll
    for (int s = 128; s > 0; s >>= 1) {
        if (tid < s) red[tid] += red[tid + s];
        __syncthreads();
    }
    if (tid == 0) g_partial2[blockIdx.x] = red[0];
}

// Stage B: single block sums 24 values in double, normalizes.
__global__ __launch_bounds__(32) void ssim_reduceB_kernel(float* __restrict__ out)
{
    __shared__ double red[32];
    const int tid = threadIdx.x;
    red[tid] = (tid < NPART2) ? (double)g_partial2[tid] : 0.0;
    __syncthreads();
#pragma unroll
    for (int st = 16; st > 0; st >>= 1) {
        if (tid < st) red[tid] += red[tid + st];
        __syncthreads();
    }
    if (tid == 0) out[0] = (float)(red[0] / NPIX);
}

extern "C" void kernel_launch(void* const* d_in, const int* in_sizes, int n_in,
                              void* d_out, int out_size)
{
    const float* img1 = (const float*)d_in[0];
    const float* img2 = (const float*)d_in[1];
    float* out = (float*)d_out;

    dim3 grid(NBLK_X, NBLK_Y, N_PLANES);
    ssim_tile_kernel<<<grid, 256, SMEM_BYTES>>>(img1, img2);
    ssim_reduceA_kernel<<<NPART2, 256>>>();
    ssim_reduceB_kernel<<<1, 32>>>(out);
}